// round 10
// baseline (speedup 1.0000x reference)
#include <cuda_runtime.h>
#include <cuda_fp16.h>
#include <stdint.h>

#define BB   2
#define NN   4096
#define DD   512
#define HH   8
#define HDIM 64
#define CQKV 1536

// Scratch (static device arrays — no runtime allocation)
__device__ __half g_qkv[(size_t)BB * NN * CQKV];    // [B,N,3,H,HD]
__device__ __half g_attn[(size_t)BB * NN * DD];     // [B,N,D]
__device__ __half g_xh[(size_t)BB * NN * DD];       // fp16 copy of x
__device__ __half g_wqkvh[(size_t)DD * CQKV];       // fp16 copy of W_qkv
__device__ __half g_wouth[(size_t)DD * DD];         // fp16 copy of W_out

// ---------------------------------------------------------------------------
// helpers
// ---------------------------------------------------------------------------
__device__ __forceinline__ uint32_t packh2(float lo, float hi) {
    __half2 h = __floats2half2_rn(lo, hi);
    return *(uint32_t*)&h;
}

__device__ __forceinline__ void mma16(float* c,
    uint32_t a0, uint32_t a1, uint32_t a2, uint32_t a3,
    uint32_t b0, uint32_t b1)
{
    asm volatile(
        "mma.sync.aligned.m16n8k16.row.col.f32.f16.f16.f32 "
        "{%0,%1,%2,%3}, {%4,%5,%6,%7}, {%8,%9}, {%0,%1,%2,%3};"
        : "+f"(c[0]), "+f"(c[1]), "+f"(c[2]), "+f"(c[3])
        : "r"(a0), "r"(a1), "r"(a2), "r"(a3), "r"(b0), "r"(b1));
}

__device__ __forceinline__ void cp16(uint32_t dst, const void* src) {
    asm volatile("cp.async.cg.shared.global [%0], [%1], 16;"
                 :: "r"(dst), "l"(src));
}
#define CP_COMMIT() asm volatile("cp.async.commit_group;")
#define CP_WAIT1()  asm volatile("cp.async.wait_group 1;")

__device__ __forceinline__ void ldsm4(uint32_t& r0, uint32_t& r1,
                                      uint32_t& r2, uint32_t& r3, uint32_t a) {
    asm volatile("ldmatrix.sync.aligned.m8n8.x4.shared.b16 {%0,%1,%2,%3}, [%4];"
        : "=r"(r0), "=r"(r1), "=r"(r2), "=r"(r3) : "r"(a));
}
__device__ __forceinline__ void ldsm4t(uint32_t& r0, uint32_t& r1,
                                       uint32_t& r2, uint32_t& r3, uint32_t a) {
    asm volatile("ldmatrix.sync.aligned.m8n8.x4.trans.shared.b16 {%0,%1,%2,%3}, [%4];"
        : "=r"(r0), "=r"(r1), "=r"(r2), "=r"(r3) : "r"(a));
}

// ---------------------------------------------------------------------------
// fp32 -> fp16 conversion (one-time)
// ---------------------------------------------------------------------------
__global__ __launch_bounds__(256) void f2h_kernel(
    const float4* __restrict__ src, uint2* __restrict__ dst, int n4)
{
    const int i = blockIdx.x * 256 + threadIdx.x;
    if (i < n4) {
        float4 v = src[i];
        dst[i] = make_uint2(packh2(v.x, v.y), packh2(v.z, v.w));
    }
}

// ---------------------------------------------------------------------------
// fp16 GEMM: C = A[M,512] @ W[512,Nc] + bias.
// BM=256, BN=128, BK=32, 512 threads (16 warps, 4x4), warp tile 64x32.
// 3 cp16/thread/iter (ratio 3 LDGSTS:HMMA, was 4) -- LSU-issue relief.
// Per-stage smem: A 256x80=20480 B + B 32x272=8704 B = 29184 B; 3 stages.
// ---------------------------------------------------------------------------
#define GEMM_BUFB 29184
#define GEMM_SMEM (3 * GEMM_BUFB)
#define GEMM_K    512
#define GEMM_NK   16

template<bool C_HALF>
__global__ __launch_bounds__(512, 1) void gemm_h(
    const __half* __restrict__ A, const __half* __restrict__ W,
    const float* __restrict__ bias, void* __restrict__ Cp, int Nc)
{
    extern __shared__ char gsm[];
    const uint32_t sb = (uint32_t)__cvta_generic_to_shared(gsm);

    const int tid  = threadIdx.x;
    const int lane = tid & 31;
    const int warp = tid >> 5;        // 0..15
    const int wm = warp >> 2;         // 0..3
    const int wn = warp & 3;          // 0..3
    const int r0 = lane >> 2;
    const int q  = lane & 3;
    const int row0 = blockIdx.y * 256;
    const int col0 = blockIdx.x * 128;

    // cp.async staging geometry (3 ops/thread)
    const int arow = tid >> 2;        // 0..127 (+128)
    const int adc  = tid & 3;         // 16B chunk in k
    const int brow = tid >> 4;        // 0..31
    const int bnc  = tid & 15;        // 16B chunk in n

    const __half* Ag = A + (size_t)(row0 + arow) * GEMM_K + adc * 8;
    const __half* Wg = W + (size_t)brow * Nc + col0 + bnc * 8;

    // fragment base addresses
    const uint32_t a_base = sb + (wm * 64 + (lane & 15)) * 80 + (lane >> 4) * 16;
    const uint32_t b_base = sb + 20480 +
        ((lane & 7) + ((lane >> 3) & 1) * 8) * 272 + wn * 64 + (lane >> 4) * 16;

    float acc[4][4][4];
#pragma unroll
    for (int i = 0; i < 4; ++i)
#pragma unroll
        for (int j = 0; j < 4; ++j)
#pragma unroll
            for (int v = 0; v < 4; ++v) acc[i][j][v] = 0.f;

    // stage K-slab s into buffer s%3
    auto stage = [&](int s) {
        const int k0 = s * 32;
        const uint32_t nb = (uint32_t)(s % 3) * GEMM_BUFB;
        cp16(sb + nb + arow * 80 + adc * 16, Ag + k0);
        cp16(sb + nb + (arow + 128) * 80 + adc * 16, Ag + (size_t)128 * GEMM_K + k0);
        cp16(sb + nb + 20480 + brow * 272 + bnc * 16, Wg + (size_t)k0 * Nc);
    };

    // prologue: slabs 0,1
    stage(0); CP_COMMIT();
    stage(1); CP_COMMIT();
    CP_WAIT1();            // slab 0 complete
    __syncthreads();

    for (int it = 0; it < GEMM_NK; ++it) {
        if (it + 2 < GEMM_NK) stage(it + 2);
        CP_COMMIT();

        const uint32_t bufo = (uint32_t)(it % 3) * GEMM_BUFB;
#pragma unroll
        for (int kk = 0; kk < 2; ++kk) {
            uint32_t a[4][4];
#pragma unroll
            for (int mt = 0; mt < 4; ++mt)
                ldsm4(a[mt][0], a[mt][1], a[mt][2], a[mt][3],
                      a_base + bufo + mt * 1280 + kk * 32);
#pragma unroll
            for (int ntp = 0; ntp < 2; ++ntp) {
                uint32_t b0, b1, b2, b3;
                ldsm4t(b0, b1, b2, b3, b_base + bufo + kk * 4352 + ntp * 32);
#pragma unroll
                for (int mt = 0; mt < 4; ++mt) {
                    mma16(acc[mt][2 * ntp],     a[mt][0], a[mt][1], a[mt][2], a[mt][3], b0, b1);
                    mma16(acc[mt][2 * ntp + 1], a[mt][0], a[mt][1], a[mt][2], a[mt][3], b2, b3);
                }
            }
        }

        CP_WAIT1();        // slab it+1 complete
        __syncthreads();
    }

    // epilogue: bias + store
#pragma unroll
    for (int mt = 0; mt < 4; ++mt) {
        const int r = row0 + wm * 64 + mt * 16 + r0;
#pragma unroll
        for (int nt = 0; nt < 4; ++nt) {
            const int c = col0 + wn * 32 + nt * 8 + 2 * q;
            const float bx = bias[c], by = bias[c + 1];
            if (C_HALF) {
                __half* Ch = (__half*)Cp;
                *(uint32_t*)(Ch + (size_t)r * Nc + c)       = packh2(acc[mt][nt][0] + bx, acc[mt][nt][1] + by);
                *(uint32_t*)(Ch + (size_t)(r + 8) * Nc + c) = packh2(acc[mt][nt][2] + bx, acc[mt][nt][3] + by);
            } else {
                float* Cf = (float*)Cp;
                float2 v0 = { acc[mt][nt][0] + bx, acc[mt][nt][1] + by };
                float2 v1 = { acc[mt][nt][2] + bx, acc[mt][nt][3] + by };
                *(float2*)&Cf[(size_t)r * Nc + c] = v0;
                *(float2*)&Cf[(size_t)(r + 8) * Nc + c] = v1;
            }
        }
    }
}

// ---------------------------------------------------------------------------
// Flash attention fp16 (R6, passing): BM=128, BN=64, 3-stage cp.async K/V
// pipeline + dedicated Q region (128x144 B), ldmatrix frags, exp2 softmax.
// smem: 3 x 18432 + 18432 = 73728 B. 2 CTAs/SM.
// ---------------------------------------------------------------------------
#define FLASH_BUFB 18432
#define FLASH_QOFF (3 * FLASH_BUFB)
#define FLASH_SMEM (FLASH_QOFF + 18432)

__global__ __launch_bounds__(256, 2) void flash_h(
    const __half* __restrict__ qkv, __half* __restrict__ outh)
{
    extern __shared__ char fss[];
    const uint32_t sb = (uint32_t)__cvta_generic_to_shared(fss);

    const int tid  = threadIdx.x;
    const int lane = tid & 31;
    const int warp = tid >> 5;
    const int r0 = lane >> 2;
    const int q  = lane & 3;

    const int idx = blockIdx.x;          // heavy qt first
    const int qt  = 31 - (idx >> 4);
    const int h   = idx & 7;
    const int b   = (idx >> 3) & 1;
    const float cexp = 0.125f * 1.44269504089f;   // scale * log2(e)

    const int srow = tid >> 3;           // 0..31 (+32)
    const int sdc  = tid & 7;            // 16B chunk in d

    const __half* qb = qkv + ((size_t)b * NN + (size_t)qt * 128) * CQKV + h * HDIM;
    const __half* kb = qkv + (size_t)b * NN * CQKV + DD + h * HDIM;
    const __half* vb = qkv + (size_t)b * NN * CQKV + 2 * DD + h * HDIM;

    const int ktmax = 2 * qt + 1;

    {
#pragma unroll
        for (int i = 0; i < 4; ++i) {
            const int c = tid + 256 * i;
            const int row = c >> 3, dc = c & 7;
            cp16(sb + FLASH_QOFF + row * 144 + dc * 16, qb + (size_t)row * CQKV + dc * 8);
        }
        cp16(sb + srow * 144 + sdc * 16, kb + (size_t)srow * CQKV + sdc * 8);
        cp16(sb + (srow + 32) * 144 + sdc * 16, kb + (size_t)(srow + 32) * CQKV + sdc * 8);
        cp16(sb + 9216 + srow * 144 + sdc * 16, vb + (size_t)srow * CQKV + sdc * 8);
        cp16(sb + 9216 + (srow + 32) * 144 + sdc * 16, vb + (size_t)(srow + 32) * CQKV + sdc * 8);
        CP_COMMIT();

        const __half* kbt = kb + (size_t)64 * CQKV;
        const __half* vbt = vb + (size_t)64 * CQKV;
        const uint32_t nb = FLASH_BUFB;
        cp16(sb + nb + srow * 144 + sdc * 16, kbt + (size_t)srow * CQKV + sdc * 8);
        cp16(sb + nb + (srow + 32) * 144 + sdc * 16, kbt + (size_t)(srow + 32) * CQKV + sdc * 8);
        cp16(sb + nb + 9216 + srow * 144 + sdc * 16, vbt + (size_t)srow * CQKV + sdc * 8);
        cp16(sb + nb + 9216 + (srow + 32) * 144 + sdc * 16, vbt + (size_t)(srow + 32) * CQKV + sdc * 8);
        CP_COMMIT();
    }
    CP_WAIT1();
    __syncthreads();

    uint32_t qa[4][4];
    {
        const uint32_t q_base = sb + FLASH_QOFF +
            (warp * 16 + (lane & 15)) * 144 + (lane >> 4) * 16;
#pragma unroll
        for (int kk = 0; kk < 4; ++kk)
            ldsm4(qa[kk][0], qa[kk][1], qa[kk][2], qa[kk][3], q_base + kk * 32);
    }

    const uint32_t k_base = sb + ((lane & 7) + ((lane >> 3) & 1) * 8) * 144 + (lane >> 4) * 16;
    const uint32_t v_base = k_base + 9216;

    float o[8][4];
#pragma unroll
    for (int t = 0; t < 8; ++t)
#pragma unroll
        for (int v = 0; v < 4; ++v) o[t][v] = 0.f;
    float m0 = -1e30f, m1 = -1e30f, l0 = 0.f, l1 = 0.f;

    const int row_g0 = qt * 128 + warp * 16 + r0;

    int buf = 0;
    for (int kt = 0; kt <= ktmax; ++kt) {
        const uint32_t bufo = (uint32_t)buf * FLASH_BUFB;
        buf = (buf == 2) ? 0 : buf + 1;

        if (kt + 2 <= ktmax) {
            const int s = (kt + 2) % 3;
            const uint32_t nb = (uint32_t)s * FLASH_BUFB;
            const __half* kbt = kb + (size_t)((kt + 2) * 64) * CQKV;
            const __half* vbt = vb + (size_t)((kt + 2) * 64) * CQKV;
            cp16(sb + nb + srow * 144 + sdc * 16, kbt + (size_t)srow * CQKV + sdc * 8);
            cp16(sb + nb + (srow + 32) * 144 + sdc * 16, kbt + (size_t)(srow + 32) * CQKV + sdc * 8);
            cp16(sb + nb + 9216 + srow * 144 + sdc * 16, vbt + (size_t)srow * CQKV + sdc * 8);
            cp16(sb + nb + 9216 + (srow + 32) * 144 + sdc * 16, vbt + (size_t)(srow + 32) * CQKV + sdc * 8);
        }
        CP_COMMIT();

        float s[8][4];
#pragma unroll
        for (int nt = 0; nt < 8; ++nt)
#pragma unroll
            for (int v = 0; v < 4; ++v) s[nt][v] = 0.f;

#pragma unroll
        for (int kk = 0; kk < 4; ++kk) {
#pragma unroll
            for (int ntp = 0; ntp < 4; ++ntp) {
                uint32_t b0, b1, b2, b3;
                ldsm4(b0, b1, b2, b3, k_base + bufo + ntp * 2304 + kk * 32);
                mma16(s[2 * ntp],     qa[kk][0], qa[kk][1], qa[kk][2], qa[kk][3], b0, b2);
                mma16(s[2 * ntp + 1], qa[kk][0], qa[kk][1], qa[kk][2], qa[kk][3], b1, b3);
            }
        }

#pragma unroll
        for (int nt = 0; nt < 8; ++nt) {
            s[nt][0] *= cexp; s[nt][1] *= cexp;
            s[nt][2] *= cexp; s[nt][3] *= cexp;
        }

        if (kt >= 2 * qt) {
            const int cb = kt * 64 + 2 * q;
#pragma unroll
            for (int nt = 0; nt < 8; ++nt) {
                const int c = cb + nt * 8;
                if (c     > row_g0)     s[nt][0] = -1e30f;
                if (c + 1 > row_g0)     s[nt][1] = -1e30f;
                if (c     > row_g0 + 8) s[nt][2] = -1e30f;
                if (c + 1 > row_g0 + 8) s[nt][3] = -1e30f;
            }
        }

        float mx0 = -1e30f, mx1 = -1e30f;
#pragma unroll
        for (int nt = 0; nt < 8; ++nt) {
            mx0 = fmaxf(mx0, fmaxf(s[nt][0], s[nt][1]));
            mx1 = fmaxf(mx1, fmaxf(s[nt][2], s[nt][3]));
        }
        mx0 = fmaxf(mx0, __shfl_xor_sync(0xffffffffu, mx0, 1));
        mx0 = fmaxf(mx0, __shfl_xor_sync(0xffffffffu, mx0, 2));
        mx1 = fmaxf(mx1, __shfl_xor_sync(0xffffffffu, mx1, 1));
        mx1 = fmaxf(mx1, __shfl_xor_sync(0xffffffffu, mx1, 2));

        const float mn0 = fmaxf(m0, mx0);
        const float mn1 = fmaxf(m1, mx1);
        float sum0 = 0.f, sum1 = 0.f;
#pragma unroll
        for (int nt = 0; nt < 8; ++nt) {
            s[nt][0] = exp2f(s[nt][0] - mn0);
            s[nt][1] = exp2f(s[nt][1] - mn0);
            s[nt][2] = exp2f(s[nt][2] - mn1);
            s[nt][3] = exp2f(s[nt][3] - mn1);
            sum0 += s[nt][0] + s[nt][1];
            sum1 += s[nt][2] + s[nt][3];
        }
        sum0 += __shfl_xor_sync(0xffffffffu, sum0, 1);
        sum0 += __shfl_xor_sync(0xffffffffu, sum0, 2);
        sum1 += __shfl_xor_sync(0xffffffffu, sum1, 1);
        sum1 += __shfl_xor_sync(0xffffffffu, sum1, 2);

        const float al0 = exp2f(m0 - mn0);
        const float al1 = exp2f(m1 - mn1);
        m0 = mn0; m1 = mn1;
        l0 = l0 * al0 + sum0;
        l1 = l1 * al1 + sum1;
#pragma unroll
        for (int t = 0; t < 8; ++t) {
            o[t][0] *= al0; o[t][1] *= al0;
            o[t][2] *= al1; o[t][3] *= al1;
        }

#pragma unroll
        for (int kk = 0; kk < 4; ++kk) {
            const uint32_t a0 = packh2(s[2 * kk][0],     s[2 * kk][1]);
            const uint32_t a1 = packh2(s[2 * kk][2],     s[2 * kk][3]);
            const uint32_t a2 = packh2(s[2 * kk + 1][0], s[2 * kk + 1][1]);
            const uint32_t a3 = packh2(s[2 * kk + 1][2], s[2 * kk + 1][3]);
#pragma unroll
            for (int dtp = 0; dtp < 4; ++dtp) {
                uint32_t b0, b1, b2, b3;
                ldsm4t(b0, b1, b2, b3, v_base + bufo + kk * 2304 + dtp * 32);
                mma16(o[2 * dtp],     a0, a1, a2, a3, b0, b1);
                mma16(o[2 * dtp + 1], a0, a1, a2, a3, b2, b3);
            }
        }

        CP_WAIT1();
        __syncthreads();
    }

    {
        const float il0 = 1.f / l0;
        const float il1 = 1.f / l1;
        __half* ob = outh + ((size_t)b * NN + (size_t)qt * 128 + warp * 16 + r0) * DD + h * HDIM;
#pragma unroll
        for (int dt = 0; dt < 8; ++dt) {
            *(uint32_t*)(ob + dt * 8 + 2 * q) =
                packh2(o[dt][0] * il0, o[dt][1] * il0);
            *(uint32_t*)(ob + (size_t)8 * DD + dt * 8 + 2 * q) =
                packh2(o[dt][2] * il1, o[dt][3] * il1);
        }
    }
}

// ---------------------------------------------------------------------------
extern "C" void kernel_launch(void* const* d_in, const int* in_sizes, int n_in,
                              void* d_out, int out_size)
{
    (void)in_sizes; (void)n_in; (void)out_size;
    const float* x    = (const float*)d_in[0];
    const float* Wqkv = (const float*)d_in[1];
    const float* bqkv = (const float*)d_in[2];
    const float* Wout = (const float*)d_in[3];
    const float* bout = (const float*)d_in[4];
    float* out = (float*)d_out;

    __half *qkv, *attn, *xh, *wqkvh, *wouth;
    cudaGetSymbolAddress((void**)&qkv, g_qkv);
    cudaGetSymbolAddress((void**)&attn, g_attn);
    cudaGetSymbolAddress((void**)&xh, g_xh);
    cudaGetSymbolAddress((void**)&wqkvh, g_wqkvh);
    cudaGetSymbolAddress((void**)&wouth, g_wouth);

    static int set_attr = 0;
    if (!set_attr) {
        cudaFuncSetAttribute(gemm_h<true>,  cudaFuncAttributeMaxDynamicSharedMemorySize, GEMM_SMEM);
        cudaFuncSetAttribute(gemm_h<false>, cudaFuncAttributeMaxDynamicSharedMemorySize, GEMM_SMEM);
        cudaFuncSetAttribute(flash_h, cudaFuncAttributeMaxDynamicSharedMemorySize, FLASH_SMEM);
        set_attr = 1;
    }

    // 0) fp32 -> fp16 conversions
    f2h_kernel<<<(BB * NN * DD / 4 + 255) / 256, 256>>>((const float4*)x, (uint2*)xh, BB * NN * DD / 4);
    f2h_kernel<<<(DD * CQKV / 4 + 255) / 256, 256>>>((const float4*)Wqkv, (uint2*)wqkvh, DD * CQKV / 4);
    f2h_kernel<<<(DD * DD / 4 + 255) / 256, 256>>>((const float4*)Wout, (uint2*)wouth, DD * DD / 4);

    // 1) QKV projection: BM=256 tiles, grid (12, 32)
    {
        dim3 grid(CQKV / 128, (BB * NN) / 256);
        gemm_h<true><<<grid, 512, GEMM_SMEM>>>(xh, wqkvh, bqkv, qkv, CQKV);
    }

    // 2) causal flash attention
    flash_h<<<512, 256, FLASH_SMEM>>>(qkv, attn);

    // 3) output projection: grid (4, 32)
    {
        dim3 grid(DD / 128, (BB * NN) / 256);
        gemm_h<false><<<grid, 512, GEMM_SMEM>>>(attn, wouth, bout, out, DD);
    }
}

// round 12
// speedup vs baseline: 1.5880x; 1.5880x over previous
#include <cuda_runtime.h>
#include <cuda_fp16.h>
#include <stdint.h>

#define BB   2
#define NN   4096
#define DD   512
#define HH   8
#define HDIM 64
#define CQKV 1536

// Scratch (static device arrays — no runtime allocation)
__device__ __half g_qkv[(size_t)BB * NN * CQKV];    // [B,N,3,H,HD]
__device__ __half g_attn[(size_t)BB * NN * DD];     // [B,N,D]
__device__ __half g_xh[(size_t)BB * NN * DD];       // fp16 copy of x
__device__ __half g_wqkvh[(size_t)DD * CQKV];       // fp16 copy of W_qkv
__device__ __half g_wouth[(size_t)DD * DD];         // fp16 copy of W_out

// ---------------------------------------------------------------------------
// helpers
// ---------------------------------------------------------------------------
__device__ __forceinline__ uint32_t packh2(float lo, float hi) {
    __half2 h = __floats2half2_rn(lo, hi);
    return *(uint32_t*)&h;
}

__device__ __forceinline__ void mma16(float* c,
    uint32_t a0, uint32_t a1, uint32_t a2, uint32_t a3,
    uint32_t b0, uint32_t b1)
{
    asm volatile(
        "mma.sync.aligned.m16n8k16.row.col.f32.f16.f16.f32 "
        "{%0,%1,%2,%3}, {%4,%5,%6,%7}, {%8,%9}, {%0,%1,%2,%3};"
        : "+f"(c[0]), "+f"(c[1]), "+f"(c[2]), "+f"(c[3])
        : "r"(a0), "r"(a1), "r"(a2), "r"(a3), "r"(b0), "r"(b1));
}

__device__ __forceinline__ void cp16(uint32_t dst, const void* src) {
    asm volatile("cp.async.cg.shared.global [%0], [%1], 16;"
                 :: "r"(dst), "l"(src));
}
#define CP_COMMIT() asm volatile("cp.async.commit_group;")
#define CP_WAIT1()  asm volatile("cp.async.wait_group 1;")
#define CP_WAIT2()  asm volatile("cp.async.wait_group 2;")

__device__ __forceinline__ void ldsm4(uint32_t& r0, uint32_t& r1,
                                      uint32_t& r2, uint32_t& r3, uint32_t a) {
    asm volatile("ldmatrix.sync.aligned.m8n8.x4.shared.b16 {%0,%1,%2,%3}, [%4];"
        : "=r"(r0), "=r"(r1), "=r"(r2), "=r"(r3) : "r"(a));
}
__device__ __forceinline__ void ldsm4t(uint32_t& r0, uint32_t& r1,
                                       uint32_t& r2, uint32_t& r3, uint32_t a) {
    asm volatile("ldmatrix.sync.aligned.m8n8.x4.trans.shared.b16 {%0,%1,%2,%3}, [%4];"
        : "=r"(r0), "=r"(r1), "=r"(r2), "=r"(r3) : "r"(a));
}

// ---------------------------------------------------------------------------
// merged fp32 -> fp16 conversion for x, W_qkv, W_out (one launch)
// ---------------------------------------------------------------------------
#define N4_X  (BB * NN * DD / 4)          // 1048576
#define N4_WQ (DD * CQKV / 4)             // 196608
#define N4_WO (DD * DD / 4)               // 65536

__global__ __launch_bounds__(256) void f2h_all(
    const float4* __restrict__ x, const float4* __restrict__ wq,
    const float4* __restrict__ wo, uint2* __restrict__ xh,
    uint2* __restrict__ wqh, uint2* __restrict__ woh)
{
    const int i = blockIdx.x * 256 + threadIdx.x;
    const float4* s;
    uint2* d;
    int j;
    if (i < N4_X)                      { s = x;  d = xh;  j = i; }
    else if (i < N4_X + N4_WQ)         { s = wq; d = wqh; j = i - N4_X; }
    else if (i < N4_X + N4_WQ + N4_WO) { s = wo; d = woh; j = i - N4_X - N4_WQ; }
    else return;
    float4 v = s[j];
    d[j] = make_uint2(packh2(v.x, v.y), packh2(v.z, v.w));
}

// ---------------------------------------------------------------------------
// fp16 GEMM: C = A[M,512] @ W[512,Nc] + bias.
// BM=128, BN=128, BK=32. 128 threads, 4 warps in 2x2, warp tile 64x64.
// LDSM traffic 32 KB/CTA/iter (was 48 KB with 2x4 warps) -> crossbar relief.
// 4-stage cp.async pipeline (R6-proven). 2 CTAs/SM.
// Per-stage smem: A 128x80=10240 B + B 32x272=8704 B = 18944 B; 4 stages.
// ---------------------------------------------------------------------------
#define GEMM_BUFB 18944
#define GEMM_SMEM (4 * GEMM_BUFB)
#define GEMM_K    512
#define GEMM_NK   16

template<bool C_HALF>
__global__ __launch_bounds__(128, 2) void gemm_h(
    const __half* __restrict__ A, const __half* __restrict__ W,
    const float* __restrict__ bias, void* __restrict__ Cp, int Nc)
{
    extern __shared__ char gsm[];
    const uint32_t sb = (uint32_t)__cvta_generic_to_shared(gsm);

    const int tid  = threadIdx.x;
    const int lane = tid & 31;
    const int warp = tid >> 5;        // 0..3
    const int wm = warp >> 1;         // 0..1
    const int wn = warp & 1;          // 0..1
    const int r0 = lane >> 2;
    const int q  = lane & 3;
    const int row0 = blockIdx.y * 128;
    const int col0 = blockIdx.x * 128;

    // fragment base addresses
    const uint32_t a_base = sb + (wm * 64 + (lane & 15)) * 80 + (lane >> 4) * 16;
    const uint32_t b_base = sb + 10240 +
        ((lane & 7) + ((lane >> 3) & 1) * 8) * 272 + wn * 128 + (lane >> 4) * 16;

    float acc[4][8][4];
#pragma unroll
    for (int i = 0; i < 4; ++i)
#pragma unroll
        for (int j = 0; j < 8; ++j)
#pragma unroll
            for (int v = 0; v < 4; ++v) acc[i][j][v] = 0.f;

    // stage K-slab s into buffer s&3 (1024 chunks total, 8 cp16/thread)
    auto stage = [&](int s) {
        const int k0 = s * 32;
        const uint32_t nb = (uint32_t)(s & 3) * GEMM_BUFB;
#pragma unroll
        for (int i = 0; i < 4; ++i) {
            const int idx = tid + 128 * i;        // 0..511
            const int ar = idx >> 2, ac = idx & 3;     // A: 128 rows x 4 chunks
            cp16(sb + nb + ar * 80 + ac * 16,
                 A + (size_t)(row0 + ar) * GEMM_K + k0 + ac * 8);
            const int br = idx >> 4, bc = idx & 15;    // B: 32 rows x 16 chunks
            cp16(sb + nb + 10240 + br * 272 + bc * 16,
                 W + (size_t)(k0 + br) * Nc + col0 + bc * 8);
        }
    };

    // prologue: slabs 0,1,2
    stage(0); CP_COMMIT();
    stage(1); CP_COMMIT();
    stage(2); CP_COMMIT();
    CP_WAIT2();            // slab 0 complete
    __syncthreads();

    for (int it = 0; it < GEMM_NK; ++it) {
        if (it + 3 < GEMM_NK) stage(it + 3);
        CP_COMMIT();

        const uint32_t bufo = (uint32_t)(it & 3) * GEMM_BUFB;
#pragma unroll
        for (int kk = 0; kk < 2; ++kk) {
            uint32_t a[4][4];
#pragma unroll
            for (int mt = 0; mt < 4; ++mt)
                ldsm4(a[mt][0], a[mt][1], a[mt][2], a[mt][3],
                      a_base + bufo + mt * 1280 + kk * 32);
#pragma unroll
            for (int ntp = 0; ntp < 4; ++ntp) {
                uint32_t b0, b1, b2, b3;
                ldsm4t(b0, b1, b2, b3, b_base + bufo + kk * 4352 + ntp * 32);
#pragma unroll
                for (int mt = 0; mt < 4; ++mt) {
                    mma16(acc[mt][2 * ntp],     a[mt][0], a[mt][1], a[mt][2], a[mt][3], b0, b1);
                    mma16(acc[mt][2 * ntp + 1], a[mt][0], a[mt][1], a[mt][2], a[mt][3], b2, b3);
                }
            }
        }

        CP_WAIT2();        // slab it+1 complete
        __syncthreads();
    }

    // epilogue: bias + store
#pragma unroll
    for (int mt = 0; mt < 4; ++mt) {
        const int r = row0 + wm * 64 + mt * 16 + r0;
#pragma unroll
        for (int nt = 0; nt < 8; ++nt) {
            const int c = col0 + wn * 64 + nt * 8 + 2 * q;
            const float bx = bias[c], by = bias[c + 1];
            if (C_HALF) {
                __half* Ch = (__half*)Cp;
                *(uint32_t*)(Ch + (size_t)r * Nc + c)       = packh2(acc[mt][nt][0] + bx, acc[mt][nt][1] + by);
                *(uint32_t*)(Ch + (size_t)(r + 8) * Nc + c) = packh2(acc[mt][nt][2] + bx, acc[mt][nt][3] + by);
            } else {
                float* Cf = (float*)Cp;
                float2 v0 = { acc[mt][nt][0] + bx, acc[mt][nt][1] + by };
                float2 v1 = { acc[mt][nt][2] + bx, acc[mt][nt][3] + by };
                *(float2*)&Cf[(size_t)r * Nc + c] = v0;
                *(float2*)&Cf[(size_t)(r + 8) * Nc + c] = v1;
            }
        }
    }
}

// ---------------------------------------------------------------------------
// Flash attention fp16 (passing, unchanged): BM=128, BN=64, 3-stage cp.async
// K/V pipeline + dedicated Q region (128x144 B), ldmatrix frags, exp2 softmax.
// smem: 3 x 18432 + 18432 = 73728 B. 2 CTAs/SM.
// ---------------------------------------------------------------------------
#define FLASH_BUFB 18432
#define FLASH_QOFF (3 * FLASH_BUFB)
#define FLASH_SMEM (FLASH_QOFF + 18432)

__global__ __launch_bounds__(256, 2) void flash_h(
    const __half* __restrict__ qkv, __half* __restrict__ outh)
{
    extern __shared__ char fss[];
    const uint32_t sb = (uint32_t)__cvta_generic_to_shared(fss);

    const int tid  = threadIdx.x;
    const int lane = tid & 31;
    const int warp = tid >> 5;
    const int r0 = lane >> 2;
    const int q  = lane & 3;

    const int idx = blockIdx.x;          // heavy qt first
    const int qt  = 31 - (idx >> 4);
    const int h   = idx & 7;
    const int b   = (idx >> 3) & 1;
    const float cexp = 0.125f * 1.44269504089f;   // scale * log2(e)

    const int srow = tid >> 3;           // 0..31 (+32)
    const int sdc  = tid & 7;            // 16B chunk in d

    const __half* qb = qkv + ((size_t)b * NN + (size_t)qt * 128) * CQKV + h * HDIM;
    const __half* kb = qkv + (size_t)b * NN * CQKV + DD + h * HDIM;
    const __half* vb = qkv + (size_t)b * NN * CQKV + 2 * DD + h * HDIM;

    const int ktmax = 2 * qt + 1;

    {
#pragma unroll
        for (int i = 0; i < 4; ++i) {
            const int c = tid + 256 * i;
            const int row = c >> 3, dc = c & 7;
            cp16(sb + FLASH_QOFF + row * 144 + dc * 16, qb + (size_t)row * CQKV + dc * 8);
        }
        cp16(sb + srow * 144 + sdc * 16, kb + (size_t)srow * CQKV + sdc * 8);
        cp16(sb + (srow + 32) * 144 + sdc * 16, kb + (size_t)(srow + 32) * CQKV + sdc * 8);
        cp16(sb + 9216 + srow * 144 + sdc * 16, vb + (size_t)srow * CQKV + sdc * 8);
        cp16(sb + 9216 + (srow + 32) * 144 + sdc * 16, vb + (size_t)(srow + 32) * CQKV + sdc * 8);
        CP_COMMIT();

        const __half* kbt = kb + (size_t)64 * CQKV;
        const __half* vbt = vb + (size_t)64 * CQKV;
        const uint32_t nb = FLASH_BUFB;
        cp16(sb + nb + srow * 144 + sdc * 16, kbt + (size_t)srow * CQKV + sdc * 8);
        cp16(sb + nb + (srow + 32) * 144 + sdc * 16, kbt + (size_t)(srow + 32) * CQKV + sdc * 8);
        cp16(sb + nb + 9216 + srow * 144 + sdc * 16, vbt + (size_t)srow * CQKV + sdc * 8);
        cp16(sb + nb + 9216 + (srow + 32) * 144 + sdc * 16, vbt + (size_t)(srow + 32) * CQKV + sdc * 8);
        CP_COMMIT();
    }
    CP_WAIT1();
    __syncthreads();

    uint32_t qa[4][4];
    {
        const uint32_t q_base = sb + FLASH_QOFF +
            (warp * 16 + (lane & 15)) * 144 + (lane >> 4) * 16;
#pragma unroll
        for (int kk = 0; kk < 4; ++kk)
            ldsm4(qa[kk][0], qa[kk][1], qa[kk][2], qa[kk][3], q_base + kk * 32);
    }

    const uint32_t k_base = sb + ((lane & 7) + ((lane >> 3) & 1) * 8) * 144 + (lane >> 4) * 16;
    const uint32_t v_base = k_base + 9216;

    float o[8][4];
#pragma unroll
    for (int t = 0; t < 8; ++t)
#pragma unroll
        for (int v = 0; v < 4; ++v) o[t][v] = 0.f;
    float m0 = -1e30f, m1 = -1e30f, l0 = 0.f, l1 = 0.f;

    const int row_g0 = qt * 128 + warp * 16 + r0;

    int buf = 0;
    for (int kt = 0; kt <= ktmax; ++kt) {
        const uint32_t bufo = (uint32_t)buf * FLASH_BUFB;
        buf = (buf == 2) ? 0 : buf + 1;

        if (kt + 2 <= ktmax) {
            const int s = (kt + 2) % 3;
            const uint32_t nb = (uint32_t)s * FLASH_BUFB;
            const __half* kbt = kb + (size_t)((kt + 2) * 64) * CQKV;
            const __half* vbt = vb + (size_t)((kt + 2) * 64) * CQKV;
            cp16(sb + nb + srow * 144 + sdc * 16, kbt + (size_t)srow * CQKV + sdc * 8);
            cp16(sb + nb + (srow + 32) * 144 + sdc * 16, kbt + (size_t)(srow + 32) * CQKV + sdc * 8);
            cp16(sb + nb + 9216 + srow * 144 + sdc * 16, vbt + (size_t)srow * CQKV + sdc * 8);
            cp16(sb + nb + 9216 + (srow + 32) * 144 + sdc * 16, vbt + (size_t)(srow + 32) * CQKV + sdc * 8);
        }
        CP_COMMIT();

        float s[8][4];
#pragma unroll
        for (int nt = 0; nt < 8; ++nt)
#pragma unroll
            for (int v = 0; v < 4; ++v) s[nt][v] = 0.f;

#pragma unroll
        for (int kk = 0; kk < 4; ++kk) {
#pragma unroll
            for (int ntp = 0; ntp < 4; ++ntp) {
                uint32_t b0, b1, b2, b3;
                ldsm4(b0, b1, b2, b3, k_base + bufo + ntp * 2304 + kk * 32);
                mma16(s[2 * ntp],     qa[kk][0], qa[kk][1], qa[kk][2], qa[kk][3], b0, b2);
                mma16(s[2 * ntp + 1], qa[kk][0], qa[kk][1], qa[kk][2], qa[kk][3], b1, b3);
            }
        }

#pragma unroll
        for (int nt = 0; nt < 8; ++nt) {
            s[nt][0] *= cexp; s[nt][1] *= cexp;
            s[nt][2] *= cexp; s[nt][3] *= cexp;
        }

        if (kt >= 2 * qt) {
            const int cb = kt * 64 + 2 * q;
#pragma unroll
            for (int nt = 0; nt < 8; ++nt) {
                const int c = cb + nt * 8;
                if (c     > row_g0)     s[nt][0] = -1e30f;
                if (c + 1 > row_g0)     s[nt][1] = -1e30f;
                if (c     > row_g0 + 8) s[nt][2] = -1e30f;
                if (c + 1 > row_g0 + 8) s[nt][3] = -1e30f;
            }
        }

        float mx0 = -1e30f, mx1 = -1e30f;
#pragma unroll
        for (int nt = 0; nt < 8; ++nt) {
            mx0 = fmaxf(mx0, fmaxf(s[nt][0], s[nt][1]));
            mx1 = fmaxf(mx1, fmaxf(s[nt][2], s[nt][3]));
        }
        mx0 = fmaxf(mx0, __shfl_xor_sync(0xffffffffu, mx0, 1));
        mx0 = fmaxf(mx0, __shfl_xor_sync(0xffffffffu, mx0, 2));
        mx1 = fmaxf(mx1, __shfl_xor_sync(0xffffffffu, mx1, 1));
        mx1 = fmaxf(mx1, __shfl_xor_sync(0xffffffffu, mx1, 2));

        const float mn0 = fmaxf(m0, mx0);
        const float mn1 = fmaxf(m1, mx1);
        float sum0 = 0.f, sum1 = 0.f;
#pragma unroll
        for (int nt = 0; nt < 8; ++nt) {
            s[nt][0] = exp2f(s[nt][0] - mn0);
            s[nt][1] = exp2f(s[nt][1] - mn0);
            s[nt][2] = exp2f(s[nt][2] - mn1);
            s[nt][3] = exp2f(s[nt][3] - mn1);
            sum0 += s[nt][0] + s[nt][1];
            sum1 += s[nt][2] + s[nt][3];
        }
        sum0 += __shfl_xor_sync(0xffffffffu, sum0, 1);
        sum0 += __shfl_xor_sync(0xffffffffu, sum0, 2);
        sum1 += __shfl_xor_sync(0xffffffffu, sum1, 1);
        sum1 += __shfl_xor_sync(0xffffffffu, sum1, 2);

        const float al0 = exp2f(m0 - mn0);
        const float al1 = exp2f(m1 - mn1);
        m0 = mn0; m1 = mn1;
        l0 = l0 * al0 + sum0;
        l1 = l1 * al1 + sum1;
#pragma unroll
        for (int t = 0; t < 8; ++t) {
            o[t][0] *= al0; o[t][1] *= al0;
            o[t][2] *= al1; o[t][3] *= al1;
        }

#pragma unroll
        for (int kk = 0; kk < 4; ++kk) {
            const uint32_t a0 = packh2(s[2 * kk][0],     s[2 * kk][1]);
            const uint32_t a1 = packh2(s[2 * kk][2],     s[2 * kk][3]);
            const uint32_t a2 = packh2(s[2 * kk + 1][0], s[2 * kk + 1][1]);
            const uint32_t a3 = packh2(s[2 * kk + 1][2], s[2 * kk + 1][3]);
#pragma unroll
            for (int dtp = 0; dtp < 4; ++dtp) {
                uint32_t b0, b1, b2, b3;
                ldsm4t(b0, b1, b2, b3, v_base + bufo + kk * 2304 + dtp * 32);
                mma16(o[2 * dtp],     a0, a1, a2, a3, b0, b1);
                mma16(o[2 * dtp + 1], a0, a1, a2, a3, b2, b3);
            }
        }

        CP_WAIT1();
        __syncthreads();
    }

    {
        const float il0 = 1.f / l0;
        const float il1 = 1.f / l1;
        __half* ob = outh + ((size_t)b * NN + (size_t)qt * 128 + warp * 16 + r0) * DD + h * HDIM;
#pragma unroll
        for (int dt = 0; dt < 8; ++dt) {
            *(uint32_t*)(ob + dt * 8 + 2 * q) =
                packh2(o[dt][0] * il0, o[dt][1] * il0);
            *(uint32_t*)(ob + (size_t)8 * DD + dt * 8 + 2 * q) =
                packh2(o[dt][2] * il1, o[dt][3] * il1);
        }
    }
}

// ---------------------------------------------------------------------------
extern "C" void kernel_launch(void* const* d_in, const int* in_sizes, int n_in,
                              void* d_out, int out_size)
{
    (void)in_sizes; (void)n_in; (void)out_size;
    const float* x    = (const float*)d_in[0];
    const float* Wqkv = (const float*)d_in[1];
    const float* bqkv = (const float*)d_in[2];
    const float* Wout = (const float*)d_in[3];
    const float* bout = (const float*)d_in[4];
    float* out = (float*)d_out;

    __half *qkv, *attn, *xh, *wqkvh, *wouth;
    cudaGetSymbolAddress((void**)&qkv, g_qkv);
    cudaGetSymbolAddress((void**)&attn, g_attn);
    cudaGetSymbolAddress((void**)&xh, g_xh);
    cudaGetSymbolAddress((void**)&wqkvh, g_wqkvh);
    cudaGetSymbolAddress((void**)&wouth, g_wouth);

    static int set_attr = 0;
    if (!set_attr) {
        cudaFuncSetAttribute(gemm_h<true>,  cudaFuncAttributeMaxDynamicSharedMemorySize, GEMM_SMEM);
        cudaFuncSetAttribute(gemm_h<false>, cudaFuncAttributeMaxDynamicSharedMemorySize, GEMM_SMEM);
        cudaFuncSetAttribute(flash_h, cudaFuncAttributeMaxDynamicSharedMemorySize, FLASH_SMEM);
        set_attr = 1;
    }

    // 0) fp32 -> fp16 conversions (single launch)
    {
        const int n4 = N4_X + N4_WQ + N4_WO;
        f2h_all<<<(n4 + 255) / 256, 256>>>(
            (const float4*)x, (const float4*)Wqkv, (const float4*)Wout,
            (uint2*)xh, (uint2*)wqkvh, (uint2*)wouth);
    }

    // 1) QKV projection: grid (12, 64), 128 threads
    {
        dim3 grid(CQKV / 128, (BB * NN) / 128);
        gemm_h<true><<<grid, 128, GEMM_SMEM>>>(xh, wqkvh, bqkv, qkv, CQKV);
    }

    // 2) causal flash attention
    flash_h<<<512, 256, FLASH_SMEM>>>(qkv, attn);

    // 3) output projection: grid (4, 64), 128 threads
    {
        dim3 grid(DD / 128, (BB * NN) / 128);
        gemm_h<false><<<grid, 128, GEMM_SMEM>>>(attn, wouth, bout, out, DD);
    }
}

// round 13
// speedup vs baseline: 1.6756x; 1.0552x over previous
#include <cuda_runtime.h>
#include <cuda_fp16.h>
#include <stdint.h>

#define BB   2
#define NN   4096
#define DD   512
#define HH   8
#define HDIM 64
#define CQKV 1536

// Scratch (static device arrays — no runtime allocation)
__device__ __half g_qkv[(size_t)BB * NN * CQKV];    // [B,N,3,H,HD]
__device__ __half g_attn[(size_t)BB * NN * DD];     // [B,N,D]
__device__ __half g_xh[(size_t)BB * NN * DD];       // fp16 copy of x
__device__ __half g_wqkvh[(size_t)DD * CQKV];       // fp16 copy of W_qkv
__device__ __half g_wouth[(size_t)DD * DD];         // fp16 copy of W_out

// ---------------------------------------------------------------------------
// helpers
// ---------------------------------------------------------------------------
__device__ __forceinline__ uint32_t packh2(float lo, float hi) {
    __half2 h = __floats2half2_rn(lo, hi);
    return *(uint32_t*)&h;
}

__device__ __forceinline__ void mma16(float* c,
    uint32_t a0, uint32_t a1, uint32_t a2, uint32_t a3,
    uint32_t b0, uint32_t b1)
{
    asm volatile(
        "mma.sync.aligned.m16n8k16.row.col.f32.f16.f16.f32 "
        "{%0,%1,%2,%3}, {%4,%5,%6,%7}, {%8,%9}, {%0,%1,%2,%3};"
        : "+f"(c[0]), "+f"(c[1]), "+f"(c[2]), "+f"(c[3])
        : "r"(a0), "r"(a1), "r"(a2), "r"(a3), "r"(b0), "r"(b1));
}

__device__ __forceinline__ void cp16(uint32_t dst, const void* src) {
    asm volatile("cp.async.cg.shared.global [%0], [%1], 16;"
                 :: "r"(dst), "l"(src));
}
#define CP_COMMIT() asm volatile("cp.async.commit_group;")
#define CP_WAIT1()  asm volatile("cp.async.wait_group 1;")
#define CP_WAIT2()  asm volatile("cp.async.wait_group 2;")

__device__ __forceinline__ void ldsm4(uint32_t& r0, uint32_t& r1,
                                      uint32_t& r2, uint32_t& r3, uint32_t a) {
    asm volatile("ldmatrix.sync.aligned.m8n8.x4.shared.b16 {%0,%1,%2,%3}, [%4];"
        : "=r"(r0), "=r"(r1), "=r"(r2), "=r"(r3) : "r"(a));
}
__device__ __forceinline__ void ldsm4t(uint32_t& r0, uint32_t& r1,
                                       uint32_t& r2, uint32_t& r3, uint32_t a) {
    asm volatile("ldmatrix.sync.aligned.m8n8.x4.trans.shared.b16 {%0,%1,%2,%3}, [%4];"
        : "=r"(r0), "=r"(r1), "=r"(r2), "=r"(r3) : "r"(a));
}

// ---------------------------------------------------------------------------
// merged fp32 -> fp16 conversion for x, W_qkv, W_out (one launch)
// ---------------------------------------------------------------------------
#define N4_X  (BB * NN * DD / 4)          // 1048576
#define N4_WQ (DD * CQKV / 4)             // 196608
#define N4_WO (DD * DD / 4)               // 65536

__global__ __launch_bounds__(256) void f2h_all(
    const float4* __restrict__ x, const float4* __restrict__ wq,
    const float4* __restrict__ wo, uint2* __restrict__ xh,
    uint2* __restrict__ wqh, uint2* __restrict__ woh)
{
    const int i = blockIdx.x * 256 + threadIdx.x;
    const float4* s;
    uint2* d;
    int j;
    if (i < N4_X)                      { s = x;  d = xh;  j = i; }
    else if (i < N4_X + N4_WQ)         { s = wq; d = wqh; j = i - N4_X; }
    else if (i < N4_X + N4_WQ + N4_WO) { s = wo; d = woh; j = i - N4_X - N4_WQ; }
    else return;
    float4 v = s[j];
    d[j] = make_uint2(packh2(v.x, v.y), packh2(v.z, v.w));
}

// ---------------------------------------------------------------------------
// fp16 GEMM (R11 WIN, unchanged): C = A[M,512] @ W[512,Nc] + bias.
// BM=128, BN=128, BK=32. 128 threads, 4 warps in 2x2, warp tile 64x64.
// 4-stage cp.async pipeline. 2 CTAs/SM.
// ---------------------------------------------------------------------------
#define GEMM_BUFB 18944
#define GEMM_SMEM (4 * GEMM_BUFB)
#define GEMM_K    512
#define GEMM_NK   16

template<bool C_HALF>
__global__ __launch_bounds__(128, 2) void gemm_h(
    const __half* __restrict__ A, const __half* __restrict__ W,
    const float* __restrict__ bias, void* __restrict__ Cp, int Nc)
{
    extern __shared__ char gsm[];
    const uint32_t sb = (uint32_t)__cvta_generic_to_shared(gsm);

    const int tid  = threadIdx.x;
    const int lane = tid & 31;
    const int warp = tid >> 5;        // 0..3
    const int wm = warp >> 1;         // 0..1
    const int wn = warp & 1;          // 0..1
    const int r0 = lane >> 2;
    const int q  = lane & 3;
    const int row0 = blockIdx.y * 128;
    const int col0 = blockIdx.x * 128;

    const uint32_t a_base = sb + (wm * 64 + (lane & 15)) * 80 + (lane >> 4) * 16;
    const uint32_t b_base = sb + 10240 +
        ((lane & 7) + ((lane >> 3) & 1) * 8) * 272 + wn * 128 + (lane >> 4) * 16;

    float acc[4][8][4];
#pragma unroll
    for (int i = 0; i < 4; ++i)
#pragma unroll
        for (int j = 0; j < 8; ++j)
#pragma unroll
            for (int v = 0; v < 4; ++v) acc[i][j][v] = 0.f;

    auto stage = [&](int s) {
        const int k0 = s * 32;
        const uint32_t nb = (uint32_t)(s & 3) * GEMM_BUFB;
#pragma unroll
        for (int i = 0; i < 4; ++i) {
            const int idx = tid + 128 * i;
            const int ar = idx >> 2, ac = idx & 3;
            cp16(sb + nb + ar * 80 + ac * 16,
                 A + (size_t)(row0 + ar) * GEMM_K + k0 + ac * 8);
            const int br = idx >> 4, bc = idx & 15;
            cp16(sb + nb + 10240 + br * 272 + bc * 16,
                 W + (size_t)(k0 + br) * Nc + col0 + bc * 8);
        }
    };

    stage(0); CP_COMMIT();
    stage(1); CP_COMMIT();
    stage(2); CP_COMMIT();
    CP_WAIT2();
    __syncthreads();

    for (int it = 0; it < GEMM_NK; ++it) {
        if (it + 3 < GEMM_NK) stage(it + 3);
        CP_COMMIT();

        const uint32_t bufo = (uint32_t)(it & 3) * GEMM_BUFB;
#pragma unroll
        for (int kk = 0; kk < 2; ++kk) {
            uint32_t a[4][4];
#pragma unroll
            for (int mt = 0; mt < 4; ++mt)
                ldsm4(a[mt][0], a[mt][1], a[mt][2], a[mt][3],
                      a_base + bufo + mt * 1280 + kk * 32);
#pragma unroll
            for (int ntp = 0; ntp < 4; ++ntp) {
                uint32_t b0, b1, b2, b3;
                ldsm4t(b0, b1, b2, b3, b_base + bufo + kk * 4352 + ntp * 32);
#pragma unroll
                for (int mt = 0; mt < 4; ++mt) {
                    mma16(acc[mt][2 * ntp],     a[mt][0], a[mt][1], a[mt][2], a[mt][3], b0, b1);
                    mma16(acc[mt][2 * ntp + 1], a[mt][0], a[mt][1], a[mt][2], a[mt][3], b2, b3);
                }
            }
        }

        CP_WAIT2();
        __syncthreads();
    }

#pragma unroll
    for (int mt = 0; mt < 4; ++mt) {
        const int r = row0 + wm * 64 + mt * 16 + r0;
#pragma unroll
        for (int nt = 0; nt < 8; ++nt) {
            const int c = col0 + wn * 64 + nt * 8 + 2 * q;
            const float bx = bias[c], by = bias[c + 1];
            if (C_HALF) {
                __half* Ch = (__half*)Cp;
                *(uint32_t*)(Ch + (size_t)r * Nc + c)       = packh2(acc[mt][nt][0] + bx, acc[mt][nt][1] + by);
                *(uint32_t*)(Ch + (size_t)(r + 8) * Nc + c) = packh2(acc[mt][nt][2] + bx, acc[mt][nt][3] + by);
            } else {
                float* Cf = (float*)Cp;
                float2 v0 = { acc[mt][nt][0] + bx, acc[mt][nt][1] + by };
                float2 v1 = { acc[mt][nt][2] + bx, acc[mt][nt][3] + by };
                *(float2*)&Cf[(size_t)r * Nc + c] = v0;
                *(float2*)&Cf[(size_t)(r + 8) * Nc + c] = v1;
            }
        }
    }
}

// ---------------------------------------------------------------------------
// Flash attention v3: BM=128, BN=64, 128 threads / 4 warps, each warp owns
// 32 q-rows (two m16 tiles) -> every K/V ldmatrix fragment feeds 2 m-tiles,
// halving LDSM traffic per tile (crossbar relief, same lever as the GEMM).
// 3-stage cp.async K/V + dedicated Q region; exp2 softmax. 2 CTAs/SM.
// smem: 3 x 18432 + 18432 = 73728 B.
// ---------------------------------------------------------------------------
#define FLASH_BUFB 18432
#define FLASH_QOFF (3 * FLASH_BUFB)
#define FLASH_SMEM (FLASH_QOFF + 18432)

__global__ __launch_bounds__(128, 2) void flash_h(
    const __half* __restrict__ qkv, __half* __restrict__ outh)
{
    extern __shared__ char fss[];
    const uint32_t sb = (uint32_t)__cvta_generic_to_shared(fss);

    const int tid  = threadIdx.x;
    const int lane = tid & 31;
    const int warp = tid >> 5;           // 0..3
    const int r0 = lane >> 2;
    const int q  = lane & 3;

    const int idx = blockIdx.x;          // heavy qt first
    const int qt  = 31 - (idx >> 4);
    const int h   = idx & 7;
    const int b   = (idx >> 3) & 1;
    const float cexp = 0.125f * 1.44269504089f;   // scale * log2(e)

    const __half* qb = qkv + ((size_t)b * NN + (size_t)qt * 128) * CQKV + h * HDIM;
    const __half* kb = qkv + (size_t)b * NN * CQKV + DD + h * HDIM;
    const __half* vb = qkv + (size_t)b * NN * CQKV + 2 * DD + h * HDIM;

    const int ktmax = 2 * qt + 1;

    // stage K/V tile `t` into buffer `s` (1024 chunks over 128 threads)
    auto stage_kv = [&](int t, int s) {
        const uint32_t nb = (uint32_t)s * FLASH_BUFB;
        const __half* kbt = kb + (size_t)(t * 64) * CQKV;
        const __half* vbt = vb + (size_t)(t * 64) * CQKV;
#pragma unroll
        for (int i = 0; i < 4; ++i) {
            const int id = tid + 128 * i;
            const int row = id >> 3, dc = id & 7;
            cp16(sb + nb + row * 144 + dc * 16, kbt + (size_t)row * CQKV + dc * 8);
            cp16(sb + nb + 9216 + row * 144 + dc * 16, vbt + (size_t)row * CQKV + dc * 8);
        }
    };

    // ---- prologue: group0 = Q + K0/V0; group1 = K1/V1 ----
    {
#pragma unroll
        for (int i = 0; i < 8; ++i) {
            const int id = tid + 128 * i;
            const int row = id >> 3, dc = id & 7;
            cp16(sb + FLASH_QOFF + row * 144 + dc * 16, qb + (size_t)row * CQKV + dc * 8);
        }
        stage_kv(0, 0);
        CP_COMMIT();
        stage_kv(1, 1);
        CP_COMMIT();
    }
    CP_WAIT1();
    __syncthreads();

    // ---- preload Q A-fragments: two m16 tiles per warp ----
    uint32_t qa[2][4][4];
#pragma unroll
    for (int mt = 0; mt < 2; ++mt) {
        const uint32_t q_base = sb + FLASH_QOFF +
            (warp * 32 + mt * 16 + (lane & 15)) * 144 + (lane >> 4) * 16;
#pragma unroll
        for (int kk = 0; kk < 4; ++kk)
            ldsm4(qa[mt][kk][0], qa[mt][kk][1], qa[mt][kk][2], qa[mt][kk][3],
                  q_base + kk * 32);
    }

    const uint32_t k_base = sb + ((lane & 7) + ((lane >> 3) & 1) * 8) * 144 + (lane >> 4) * 16;
    const uint32_t v_base = k_base + 9216;

    float o[2][8][4];
#pragma unroll
    for (int mt = 0; mt < 2; ++mt)
#pragma unroll
        for (int t = 0; t < 8; ++t)
#pragma unroll
            for (int v = 0; v < 4; ++v) o[mt][t][v] = 0.f;
    float m[2][2] = {{-1e30f, -1e30f}, {-1e30f, -1e30f}};
    float l[2][2] = {{0.f, 0.f}, {0.f, 0.f}};

    int buf = 0;
    for (int kt = 0; kt <= ktmax; ++kt) {
        const uint32_t bufo = (uint32_t)buf * FLASH_BUFB;
        buf = (buf == 2) ? 0 : buf + 1;

        if (kt + 2 <= ktmax) stage_kv(kt + 2, (kt + 2) % 3);
        CP_COMMIT();

        // ---- S = Q @ K^T : K fragments reused across both m-tiles ----
        float s[2][8][4];
#pragma unroll
        for (int mt = 0; mt < 2; ++mt)
#pragma unroll
            for (int nt = 0; nt < 8; ++nt)
#pragma unroll
                for (int v = 0; v < 4; ++v) s[mt][nt][v] = 0.f;

#pragma unroll
        for (int kk = 0; kk < 4; ++kk) {
#pragma unroll
            for (int ntp = 0; ntp < 4; ++ntp) {
                uint32_t b0, b1, b2, b3;
                ldsm4(b0, b1, b2, b3, k_base + bufo + ntp * 2304 + kk * 32);
#pragma unroll
                for (int mt = 0; mt < 2; ++mt) {
                    mma16(s[mt][2 * ntp],     qa[mt][kk][0], qa[mt][kk][1],
                          qa[mt][kk][2], qa[mt][kk][3], b0, b2);
                    mma16(s[mt][2 * ntp + 1], qa[mt][kk][0], qa[mt][kk][1],
                          qa[mt][kk][2], qa[mt][kk][3], b1, b3);
                }
            }
        }

        // scale to log2 domain
#pragma unroll
        for (int mt = 0; mt < 2; ++mt)
#pragma unroll
            for (int nt = 0; nt < 8; ++nt) {
                s[mt][nt][0] *= cexp; s[mt][nt][1] *= cexp;
                s[mt][nt][2] *= cexp; s[mt][nt][3] *= cexp;
            }

        // ---- causal mask (near-diagonal tiles only) ----
        if (kt >= 2 * qt) {
            const int cb = kt * 64 + 2 * q;
#pragma unroll
            for (int mt = 0; mt < 2; ++mt) {
                const int rg = qt * 128 + warp * 32 + mt * 16 + r0;
#pragma unroll
                for (int nt = 0; nt < 8; ++nt) {
                    const int c = cb + nt * 8;
                    if (c     > rg)     s[mt][nt][0] = -1e30f;
                    if (c + 1 > rg)     s[mt][nt][1] = -1e30f;
                    if (c     > rg + 8) s[mt][nt][2] = -1e30f;
                    if (c + 1 > rg + 8) s[mt][nt][3] = -1e30f;
                }
            }
        }

        // ---- online softmax (exp2 domain), per m-tile ----
#pragma unroll
        for (int mt = 0; mt < 2; ++mt) {
            float mx0 = -1e30f, mx1 = -1e30f;
#pragma unroll
            for (int nt = 0; nt < 8; ++nt) {
                mx0 = fmaxf(mx0, fmaxf(s[mt][nt][0], s[mt][nt][1]));
                mx1 = fmaxf(mx1, fmaxf(s[mt][nt][2], s[mt][nt][3]));
            }
            mx0 = fmaxf(mx0, __shfl_xor_sync(0xffffffffu, mx0, 1));
            mx0 = fmaxf(mx0, __shfl_xor_sync(0xffffffffu, mx0, 2));
            mx1 = fmaxf(mx1, __shfl_xor_sync(0xffffffffu, mx1, 1));
            mx1 = fmaxf(mx1, __shfl_xor_sync(0xffffffffu, mx1, 2));

            const float mn0 = fmaxf(m[mt][0], mx0);
            const float mn1 = fmaxf(m[mt][1], mx1);
            float sum0 = 0.f, sum1 = 0.f;
#pragma unroll
            for (int nt = 0; nt < 8; ++nt) {
                s[mt][nt][0] = exp2f(s[mt][nt][0] - mn0);
                s[mt][nt][1] = exp2f(s[mt][nt][1] - mn0);
                s[mt][nt][2] = exp2f(s[mt][nt][2] - mn1);
                s[mt][nt][3] = exp2f(s[mt][nt][3] - mn1);
                sum0 += s[mt][nt][0] + s[mt][nt][1];
                sum1 += s[mt][nt][2] + s[mt][nt][3];
            }
            sum0 += __shfl_xor_sync(0xffffffffu, sum0, 1);
            sum0 += __shfl_xor_sync(0xffffffffu, sum0, 2);
            sum1 += __shfl_xor_sync(0xffffffffu, sum1, 1);
            sum1 += __shfl_xor_sync(0xffffffffu, sum1, 2);

            const float al0 = exp2f(m[mt][0] - mn0);
            const float al1 = exp2f(m[mt][1] - mn1);
            m[mt][0] = mn0; m[mt][1] = mn1;
            l[mt][0] = l[mt][0] * al0 + sum0;
            l[mt][1] = l[mt][1] * al1 + sum1;
#pragma unroll
            for (int t = 0; t < 8; ++t) {
                o[mt][t][0] *= al0; o[mt][t][1] *= al0;
                o[mt][t][2] *= al1; o[mt][t][3] *= al1;
            }
        }

        // ---- O += P @ V : V fragments reused across both m-tiles ----
#pragma unroll
        for (int kk = 0; kk < 4; ++kk) {
            uint32_t a[2][4];
#pragma unroll
            for (int mt = 0; mt < 2; ++mt) {
                a[mt][0] = packh2(s[mt][2 * kk][0],     s[mt][2 * kk][1]);
                a[mt][1] = packh2(s[mt][2 * kk][2],     s[mt][2 * kk][3]);
                a[mt][2] = packh2(s[mt][2 * kk + 1][0], s[mt][2 * kk + 1][1]);
                a[mt][3] = packh2(s[mt][2 * kk + 1][2], s[mt][2 * kk + 1][3]);
            }
#pragma unroll
            for (int dtp = 0; dtp < 4; ++dtp) {
                uint32_t b0, b1, b2, b3;
                ldsm4t(b0, b1, b2, b3, v_base + bufo + kk * 2304 + dtp * 32);
#pragma unroll
                for (int mt = 0; mt < 2; ++mt) {
                    mma16(o[mt][2 * dtp],     a[mt][0], a[mt][1], a[mt][2], a[mt][3], b0, b1);
                    mma16(o[mt][2 * dtp + 1], a[mt][0], a[mt][1], a[mt][2], a[mt][3], b2, b3);
                }
            }
        }

        CP_WAIT1();
        __syncthreads();
    }

    // ---- epilogue ----
#pragma unroll
    for (int mt = 0; mt < 2; ++mt) {
        const float il0 = 1.f / l[mt][0];
        const float il1 = 1.f / l[mt][1];
        __half* ob = outh +
            ((size_t)b * NN + (size_t)qt * 128 + warp * 32 + mt * 16 + r0) * DD + h * HDIM;
#pragma unroll
        for (int dt = 0; dt < 8; ++dt) {
            *(uint32_t*)(ob + dt * 8 + 2 * q) =
                packh2(o[mt][dt][0] * il0, o[mt][dt][1] * il0);
            *(uint32_t*)(ob + (size_t)8 * DD + dt * 8 + 2 * q) =
                packh2(o[mt][dt][2] * il1, o[mt][dt][3] * il1);
        }
    }
}

// ---------------------------------------------------------------------------
extern "C" void kernel_launch(void* const* d_in, const int* in_sizes, int n_in,
                              void* d_out, int out_size)
{
    (void)in_sizes; (void)n_in; (void)out_size;
    const float* x    = (const float*)d_in[0];
    const float* Wqkv = (const float*)d_in[1];
    const float* bqkv = (const float*)d_in[2];
    const float* Wout = (const float*)d_in[3];
    const float* bout = (const float*)d_in[4];
    float* out = (float*)d_out;

    __half *qkv, *attn, *xh, *wqkvh, *wouth;
    cudaGetSymbolAddress((void**)&qkv, g_qkv);
    cudaGetSymbolAddress((void**)&attn, g_attn);
    cudaGetSymbolAddress((void**)&xh, g_xh);
    cudaGetSymbolAddress((void**)&wqkvh, g_wqkvh);
    cudaGetSymbolAddress((void**)&wouth, g_wouth);

    static int set_attr = 0;
    if (!set_attr) {
        cudaFuncSetAttribute(gemm_h<true>,  cudaFuncAttributeMaxDynamicSharedMemorySize, GEMM_SMEM);
        cudaFuncSetAttribute(gemm_h<false>, cudaFuncAttributeMaxDynamicSharedMemorySize, GEMM_SMEM);
        cudaFuncSetAttribute(flash_h, cudaFuncAttributeMaxDynamicSharedMemorySize, FLASH_SMEM);
        set_attr = 1;
    }

    // 0) fp32 -> fp16 conversions (single launch)
    {
        const int n4 = N4_X + N4_WQ + N4_WO;
        f2h_all<<<(n4 + 255) / 256, 256>>>(
            (const float4*)x, (const float4*)Wqkv, (const float4*)Wout,
            (uint2*)xh, (uint2*)wqkvh, (uint2*)wouth);
    }

    // 1) QKV projection: grid (12, 64), 128 threads
    {
        dim3 grid(CQKV / 128, (BB * NN) / 128);
        gemm_h<true><<<grid, 128, GEMM_SMEM>>>(xh, wqkvh, bqkv, qkv, CQKV);
    }

    // 2) causal flash attention (4-warp, 32 rows/warp)
    flash_h<<<512, 128, FLASH_SMEM>>>(qkv, attn);

    // 3) output projection: grid (4, 64), 128 threads
    {
        dim3 grid(DD / 128, (BB * NN) / 128);
        gemm_h<false><<<grid, 128, GEMM_SMEM>>>(attn, wouth, bout, out, DD);
    }
}

// round 14
// speedup vs baseline: 1.7576x; 1.0490x over previous
#include <cuda_runtime.h>
#include <cuda_fp16.h>
#include <stdint.h>

#define BB   2
#define NN   4096
#define DD   512
#define HH   8
#define HDIM 64
#define CQKV 1536

// Scratch (static device arrays — no runtime allocation)
__device__ __half g_qkv[(size_t)BB * NN * CQKV];    // [B,N,3,H,HD]
__device__ __half g_attn[(size_t)BB * NN * DD];     // [B,N,D]
__device__ __half g_xh[(size_t)BB * NN * DD];       // fp16 copy of x
__device__ __half g_wqkvh[(size_t)DD * CQKV];       // fp16 copy of W_qkv
__device__ __half g_wouth[(size_t)DD * DD];         // fp16 copy of W_out

// ---------------------------------------------------------------------------
// helpers
// ---------------------------------------------------------------------------
__device__ __forceinline__ uint32_t packh2(float lo, float hi) {
    __half2 h = __floats2half2_rn(lo, hi);
    return *(uint32_t*)&h;
}

__device__ __forceinline__ uint32_t hex2(uint32_t x) {   // 2^x on f16x2
    uint32_t r;
    asm("ex2.approx.f16x2 %0, %1;" : "=r"(r) : "r"(x));
    return r;
}

__device__ __forceinline__ void mma16(float* c,
    uint32_t a0, uint32_t a1, uint32_t a2, uint32_t a3,
    uint32_t b0, uint32_t b1)
{
    asm volatile(
        "mma.sync.aligned.m16n8k16.row.col.f32.f16.f16.f32 "
        "{%0,%1,%2,%3}, {%4,%5,%6,%7}, {%8,%9}, {%0,%1,%2,%3};"
        : "+f"(c[0]), "+f"(c[1]), "+f"(c[2]), "+f"(c[3])
        : "r"(a0), "r"(a1), "r"(a2), "r"(a3), "r"(b0), "r"(b1));
}

__device__ __forceinline__ void cp16(uint32_t dst, const void* src) {
    asm volatile("cp.async.cg.shared.global [%0], [%1], 16;"
                 :: "r"(dst), "l"(src));
}
#define CP_COMMIT() asm volatile("cp.async.commit_group;")
#define CP_WAIT1()  asm volatile("cp.async.wait_group 1;")
#define CP_WAIT2()  asm volatile("cp.async.wait_group 2;")

__device__ __forceinline__ void ldsm4(uint32_t& r0, uint32_t& r1,
                                      uint32_t& r2, uint32_t& r3, uint32_t a) {
    asm volatile("ldmatrix.sync.aligned.m8n8.x4.shared.b16 {%0,%1,%2,%3}, [%4];"
        : "=r"(r0), "=r"(r1), "=r"(r2), "=r"(r3) : "r"(a));
}
__device__ __forceinline__ void ldsm4t(uint32_t& r0, uint32_t& r1,
                                       uint32_t& r2, uint32_t& r3, uint32_t a) {
    asm volatile("ldmatrix.sync.aligned.m8n8.x4.trans.shared.b16 {%0,%1,%2,%3}, [%4];"
        : "=r"(r0), "=r"(r1), "=r"(r2), "=r"(r3) : "r"(a));
}

// ---------------------------------------------------------------------------
// merged fp32 -> fp16 conversion for x, W_qkv, W_out (one launch)
// ---------------------------------------------------------------------------
#define N4_X  (BB * NN * DD / 4)          // 1048576
#define N4_WQ (DD * CQKV / 4)             // 196608
#define N4_WO (DD * DD / 4)               // 65536

__global__ __launch_bounds__(256) void f2h_all(
    const float4* __restrict__ x, const float4* __restrict__ wq,
    const float4* __restrict__ wo, uint2* __restrict__ xh,
    uint2* __restrict__ wqh, uint2* __restrict__ woh)
{
    const int i = blockIdx.x * 256 + threadIdx.x;
    const float4* s;
    uint2* d;
    int j;
    if (i < N4_X)                      { s = x;  d = xh;  j = i; }
    else if (i < N4_X + N4_WQ)         { s = wq; d = wqh; j = i - N4_X; }
    else if (i < N4_X + N4_WQ + N4_WO) { s = wo; d = woh; j = i - N4_X - N4_WQ; }
    else return;
    float4 v = s[j];
    d[j] = make_uint2(packh2(v.x, v.y), packh2(v.z, v.w));
}

// ---------------------------------------------------------------------------
// fp16 GEMM (R11 WIN, unchanged): C = A[M,512] @ W[512,Nc] + bias.
// BM=128, BN=128, BK=32. 128 threads, 4 warps in 2x2, warp tile 64x64.
// 4-stage cp.async pipeline. 2 CTAs/SM.
// ---------------------------------------------------------------------------
#define GEMM_BUFB 18944
#define GEMM_SMEM (4 * GEMM_BUFB)
#define GEMM_K    512
#define GEMM_NK   16

template<bool C_HALF>
__global__ __launch_bounds__(128, 2) void gemm_h(
    const __half* __restrict__ A, const __half* __restrict__ W,
    const float* __restrict__ bias, void* __restrict__ Cp, int Nc)
{
    extern __shared__ char gsm[];
    const uint32_t sb = (uint32_t)__cvta_generic_to_shared(gsm);

    const int tid  = threadIdx.x;
    const int lane = tid & 31;
    const int warp = tid >> 5;        // 0..3
    const int wm = warp >> 1;         // 0..1
    const int wn = warp & 1;          // 0..1
    const int r0 = lane >> 2;
    const int q  = lane & 3;
    const int row0 = blockIdx.y * 128;
    const int col0 = blockIdx.x * 128;

    const uint32_t a_base = sb + (wm * 64 + (lane & 15)) * 80 + (lane >> 4) * 16;
    const uint32_t b_base = sb + 10240 +
        ((lane & 7) + ((lane >> 3) & 1) * 8) * 272 + wn * 128 + (lane >> 4) * 16;

    float acc[4][8][4];
#pragma unroll
    for (int i = 0; i < 4; ++i)
#pragma unroll
        for (int j = 0; j < 8; ++j)
#pragma unroll
            for (int v = 0; v < 4; ++v) acc[i][j][v] = 0.f;

    auto stage = [&](int s) {
        const int k0 = s * 32;
        const uint32_t nb = (uint32_t)(s & 3) * GEMM_BUFB;
#pragma unroll
        for (int i = 0; i < 4; ++i) {
            const int idx = tid + 128 * i;
            const int ar = idx >> 2, ac = idx & 3;
            cp16(sb + nb + ar * 80 + ac * 16,
                 A + (size_t)(row0 + ar) * GEMM_K + k0 + ac * 8);
            const int br = idx >> 4, bc = idx & 15;
            cp16(sb + nb + 10240 + br * 272 + bc * 16,
                 W + (size_t)(k0 + br) * Nc + col0 + bc * 8);
        }
    };

    stage(0); CP_COMMIT();
    stage(1); CP_COMMIT();
    stage(2); CP_COMMIT();
    CP_WAIT2();
    __syncthreads();

    for (int it = 0; it < GEMM_NK; ++it) {
        if (it + 3 < GEMM_NK) stage(it + 3);
        CP_COMMIT();

        const uint32_t bufo = (uint32_t)(it & 3) * GEMM_BUFB;
#pragma unroll
        for (int kk = 0; kk < 2; ++kk) {
            uint32_t a[4][4];
#pragma unroll
            for (int mt = 0; mt < 4; ++mt)
                ldsm4(a[mt][0], a[mt][1], a[mt][2], a[mt][3],
                      a_base + bufo + mt * 1280 + kk * 32);
#pragma unroll
            for (int ntp = 0; ntp < 4; ++ntp) {
                uint32_t b0, b1, b2, b3;
                ldsm4t(b0, b1, b2, b3, b_base + bufo + kk * 4352 + ntp * 32);
#pragma unroll
                for (int mt = 0; mt < 4; ++mt) {
                    mma16(acc[mt][2 * ntp],     a[mt][0], a[mt][1], a[mt][2], a[mt][3], b0, b1);
                    mma16(acc[mt][2 * ntp + 1], a[mt][0], a[mt][1], a[mt][2], a[mt][3], b2, b3);
                }
            }
        }

        CP_WAIT2();
        __syncthreads();
    }

#pragma unroll
    for (int mt = 0; mt < 4; ++mt) {
        const int r = row0 + wm * 64 + mt * 16 + r0;
#pragma unroll
        for (int nt = 0; nt < 8; ++nt) {
            const int c = col0 + wn * 64 + nt * 8 + 2 * q;
            const float bx = bias[c], by = bias[c + 1];
            if (C_HALF) {
                __half* Ch = (__half*)Cp;
                *(uint32_t*)(Ch + (size_t)r * Nc + c)       = packh2(acc[mt][nt][0] + bx, acc[mt][nt][1] + by);
                *(uint32_t*)(Ch + (size_t)(r + 8) * Nc + c) = packh2(acc[mt][nt][2] + bx, acc[mt][nt][3] + by);
            } else {
                float* Cf = (float*)Cp;
                float2 v0 = { acc[mt][nt][0] + bx, acc[mt][nt][1] + by };
                float2 v1 = { acc[mt][nt][2] + bx, acc[mt][nt][3] + by };
                *(float2*)&Cf[(size_t)r * Nc + c] = v0;
                *(float2*)&Cf[(size_t)(r + 8) * Nc + c] = v1;
            }
        }
    }
}

// ---------------------------------------------------------------------------
// Flash attention v4: R12 structure (4 warps x 32 q-rows, K/V frag reuse)
// + f16x2 ex2 softmax (half the MUFU ops; packs reused as PV A-fragments)
// + row sums l via ones-MMA (no sum FMAs, no sum shuffles; fp32 tensor acc).
// 3-stage cp.async K/V + dedicated Q region. 2 CTAs/SM.
// ---------------------------------------------------------------------------
#define FLASH_BUFB 18432
#define FLASH_QOFF (3 * FLASH_BUFB)
#define FLASH_SMEM (FLASH_QOFF + 18432)

__global__ __launch_bounds__(128, 2) void flash_h(
    const __half* __restrict__ qkv, __half* __restrict__ outh)
{
    extern __shared__ char fss[];
    const uint32_t sb = (uint32_t)__cvta_generic_to_shared(fss);

    const int tid  = threadIdx.x;
    const int lane = tid & 31;
    const int warp = tid >> 5;           // 0..3
    const int r0 = lane >> 2;
    const int q  = lane & 3;

    const int idx = blockIdx.x;          // heavy qt first
    const int qt  = 31 - (idx >> 4);
    const int h   = idx & 7;
    const int b   = (idx >> 3) & 1;
    const float cexp = 0.125f * 1.44269504089f;   // scale * log2(e)
    const uint32_t bone = packh2(1.f, 1.f);       // ones B fragment

    const __half* qb = qkv + ((size_t)b * NN + (size_t)qt * 128) * CQKV + h * HDIM;
    const __half* kb = qkv + (size_t)b * NN * CQKV + DD + h * HDIM;
    const __half* vb = qkv + (size_t)b * NN * CQKV + 2 * DD + h * HDIM;

    const int ktmax = 2 * qt + 1;

    auto stage_kv = [&](int t, int s) {
        const uint32_t nb = (uint32_t)s * FLASH_BUFB;
        const __half* kbt = kb + (size_t)(t * 64) * CQKV;
        const __half* vbt = vb + (size_t)(t * 64) * CQKV;
#pragma unroll
        for (int i = 0; i < 4; ++i) {
            const int id = tid + 128 * i;
            const int row = id >> 3, dc = id & 7;
            cp16(sb + nb + row * 144 + dc * 16, kbt + (size_t)row * CQKV + dc * 8);
            cp16(sb + nb + 9216 + row * 144 + dc * 16, vbt + (size_t)row * CQKV + dc * 8);
        }
    };

    // ---- prologue: group0 = Q + K0/V0; group1 = K1/V1 ----
    {
#pragma unroll
        for (int i = 0; i < 8; ++i) {
            const int id = tid + 128 * i;
            const int row = id >> 3, dc = id & 7;
            cp16(sb + FLASH_QOFF + row * 144 + dc * 16, qb + (size_t)row * CQKV + dc * 8);
        }
        stage_kv(0, 0);
        CP_COMMIT();
        stage_kv(1, 1);
        CP_COMMIT();
    }
    CP_WAIT1();
    __syncthreads();

    // ---- preload Q A-fragments: two m16 tiles per warp ----
    uint32_t qa[2][4][4];
#pragma unroll
    for (int mt = 0; mt < 2; ++mt) {
        const uint32_t q_base = sb + FLASH_QOFF +
            (warp * 32 + mt * 16 + (lane & 15)) * 144 + (lane >> 4) * 16;
#pragma unroll
        for (int kk = 0; kk < 4; ++kk)
            ldsm4(qa[mt][kk][0], qa[mt][kk][1], qa[mt][kk][2], qa[mt][kk][3],
                  q_base + kk * 32);
    }

    const uint32_t k_base = sb + ((lane & 7) + ((lane >> 3) & 1) * 8) * 144 + (lane >> 4) * 16;
    const uint32_t v_base = k_base + 9216;

    float o[2][8][4];
#pragma unroll
    for (int mt = 0; mt < 2; ++mt)
#pragma unroll
        for (int t = 0; t < 8; ++t)
#pragma unroll
            for (int v = 0; v < 4; ++v) o[mt][t][v] = 0.f;
    float m[2][2] = {{-1e30f, -1e30f}, {-1e30f, -1e30f}};
    float lacc[2][4] = {{0.f, 0.f, 0.f, 0.f}, {0.f, 0.f, 0.f, 0.f}};

    int buf = 0;
    for (int kt = 0; kt <= ktmax; ++kt) {
        const uint32_t bufo = (uint32_t)buf * FLASH_BUFB;
        buf = (buf == 2) ? 0 : buf + 1;

        if (kt + 2 <= ktmax) stage_kv(kt + 2, (kt + 2) % 3);
        CP_COMMIT();

        // ---- S = Q @ K^T : K fragments reused across both m-tiles ----
        float s[2][8][4];
#pragma unroll
        for (int mt = 0; mt < 2; ++mt)
#pragma unroll
            for (int nt = 0; nt < 8; ++nt)
#pragma unroll
                for (int v = 0; v < 4; ++v) s[mt][nt][v] = 0.f;

#pragma unroll
        for (int kk = 0; kk < 4; ++kk) {
#pragma unroll
            for (int ntp = 0; ntp < 4; ++ntp) {
                uint32_t b0, b1, b2, b3;
                ldsm4(b0, b1, b2, b3, k_base + bufo + ntp * 2304 + kk * 32);
#pragma unroll
                for (int mt = 0; mt < 2; ++mt) {
                    mma16(s[mt][2 * ntp],     qa[mt][kk][0], qa[mt][kk][1],
                          qa[mt][kk][2], qa[mt][kk][3], b0, b2);
                    mma16(s[mt][2 * ntp + 1], qa[mt][kk][0], qa[mt][kk][1],
                          qa[mt][kk][2], qa[mt][kk][3], b1, b3);
                }
            }
        }

        // scale to log2 domain
#pragma unroll
        for (int mt = 0; mt < 2; ++mt)
#pragma unroll
            for (int nt = 0; nt < 8; ++nt) {
                s[mt][nt][0] *= cexp; s[mt][nt][1] *= cexp;
                s[mt][nt][2] *= cexp; s[mt][nt][3] *= cexp;
            }

        // ---- causal mask (near-diagonal tiles only) ----
        if (kt >= 2 * qt) {
            const int cb = kt * 64 + 2 * q;
#pragma unroll
            for (int mt = 0; mt < 2; ++mt) {
                const int rg = qt * 128 + warp * 32 + mt * 16 + r0;
#pragma unroll
                for (int nt = 0; nt < 8; ++nt) {
                    const int c = cb + nt * 8;
                    if (c     > rg)     s[mt][nt][0] = -1e30f;
                    if (c + 1 > rg)     s[mt][nt][1] = -1e30f;
                    if (c     > rg + 8) s[mt][nt][2] = -1e30f;
                    if (c + 1 > rg + 8) s[mt][nt][3] = -1e30f;
                }
            }
        }

        // ---- online softmax: f16x2 ex2, packs become PV A-fragments ----
        uint32_t p[2][8][2];
#pragma unroll
        for (int mt = 0; mt < 2; ++mt) {
            float mx0 = -1e30f, mx1 = -1e30f;
#pragma unroll
            for (int nt = 0; nt < 8; ++nt) {
                mx0 = fmaxf(mx0, fmaxf(s[mt][nt][0], s[mt][nt][1]));
                mx1 = fmaxf(mx1, fmaxf(s[mt][nt][2], s[mt][nt][3]));
            }
            mx0 = fmaxf(mx0, __shfl_xor_sync(0xffffffffu, mx0, 1));
            mx0 = fmaxf(mx0, __shfl_xor_sync(0xffffffffu, mx0, 2));
            mx1 = fmaxf(mx1, __shfl_xor_sync(0xffffffffu, mx1, 1));
            mx1 = fmaxf(mx1, __shfl_xor_sync(0xffffffffu, mx1, 2));

            const float mn0 = fmaxf(m[mt][0], mx0);
            const float mn1 = fmaxf(m[mt][1], mx1);
#pragma unroll
            for (int nt = 0; nt < 8; ++nt) {
                p[mt][nt][0] = hex2(packh2(s[mt][nt][0] - mn0, s[mt][nt][1] - mn0));
                p[mt][nt][1] = hex2(packh2(s[mt][nt][2] - mn1, s[mt][nt][3] - mn1));
            }

            const float al0 = exp2f(m[mt][0] - mn0);
            const float al1 = exp2f(m[mt][1] - mn1);
            m[mt][0] = mn0; m[mt][1] = mn1;
            lacc[mt][0] *= al0; lacc[mt][1] *= al0;
            lacc[mt][2] *= al1; lacc[mt][3] *= al1;
#pragma unroll
            for (int t = 0; t < 8; ++t) {
                o[mt][t][0] *= al0; o[mt][t][1] *= al0;
                o[mt][t][2] *= al1; o[mt][t][3] *= al1;
            }
        }

        // ---- O += P @ V ; l += P @ 1 (ones-MMA) ----
#pragma unroll
        for (int kk = 0; kk < 4; ++kk) {
            uint32_t a[2][4];
#pragma unroll
            for (int mt = 0; mt < 2; ++mt) {
                a[mt][0] = p[mt][2 * kk][0];
                a[mt][1] = p[mt][2 * kk][1];
                a[mt][2] = p[mt][2 * kk + 1][0];
                a[mt][3] = p[mt][2 * kk + 1][1];
                mma16(lacc[mt], a[mt][0], a[mt][1], a[mt][2], a[mt][3], bone, bone);
            }
#pragma unroll
            for (int dtp = 0; dtp < 4; ++dtp) {
                uint32_t b0, b1, b2, b3;
                ldsm4t(b0, b1, b2, b3, v_base + bufo + kk * 2304 + dtp * 32);
#pragma unroll
                for (int mt = 0; mt < 2; ++mt) {
                    mma16(o[mt][2 * dtp],     a[mt][0], a[mt][1], a[mt][2], a[mt][3], b0, b1);
                    mma16(o[mt][2 * dtp + 1], a[mt][0], a[mt][1], a[mt][2], a[mt][3], b2, b3);
                }
            }
        }

        CP_WAIT1();
        __syncthreads();
    }

    // ---- epilogue: every thread already holds its row sums in lacc ----
#pragma unroll
    for (int mt = 0; mt < 2; ++mt) {
        const float il0 = 1.f / lacc[mt][0];
        const float il1 = 1.f / lacc[mt][2];
        __half* ob = outh +
            ((size_t)b * NN + (size_t)qt * 128 + warp * 32 + mt * 16 + r0) * DD + h * HDIM;
#pragma unroll
        for (int dt = 0; dt < 8; ++dt) {
            *(uint32_t*)(ob + dt * 8 + 2 * q) =
                packh2(o[mt][dt][0] * il0, o[mt][dt][1] * il0);
            *(uint32_t*)(ob + (size_t)8 * DD + dt * 8 + 2 * q) =
                packh2(o[mt][dt][2] * il1, o[mt][dt][3] * il1);
        }
    }
}

// ---------------------------------------------------------------------------
extern "C" void kernel_launch(void* const* d_in, const int* in_sizes, int n_in,
                              void* d_out, int out_size)
{
    (void)in_sizes; (void)n_in; (void)out_size;
    const float* x    = (const float*)d_in[0];
    const float* Wqkv = (const float*)d_in[1];
    const float* bqkv = (const float*)d_in[2];
    const float* Wout = (const float*)d_in[3];
    const float* bout = (const float*)d_in[4];
    float* out = (float*)d_out;

    __half *qkv, *attn, *xh, *wqkvh, *wouth;
    cudaGetSymbolAddress((void**)&qkv, g_qkv);
    cudaGetSymbolAddress((void**)&attn, g_attn);
    cudaGetSymbolAddress((void**)&xh, g_xh);
    cudaGetSymbolAddress((void**)&wqkvh, g_wqkvh);
    cudaGetSymbolAddress((void**)&wouth, g_wouth);

    static int set_attr = 0;
    if (!set_attr) {
        cudaFuncSetAttribute(gemm_h<true>,  cudaFuncAttributeMaxDynamicSharedMemorySize, GEMM_SMEM);
        cudaFuncSetAttribute(gemm_h<false>, cudaFuncAttributeMaxDynamicSharedMemorySize, GEMM_SMEM);
        cudaFuncSetAttribute(flash_h, cudaFuncAttributeMaxDynamicSharedMemorySize, FLASH_SMEM);
        set_attr = 1;
    }

    // 0) fp32 -> fp16 conversions (single launch)
    {
        const int n4 = N4_X + N4_WQ + N4_WO;
        f2h_all<<<(n4 + 255) / 256, 256>>>(
            (const float4*)x, (const float4*)Wqkv, (const float4*)Wout,
            (uint2*)xh, (uint2*)wqkvh, (uint2*)wouth);
    }

    // 1) QKV projection: grid (12, 64), 128 threads
    {
        dim3 grid(CQKV / 128, (BB * NN) / 128);
        gemm_h<true><<<grid, 128, GEMM_SMEM>>>(xh, wqkvh, bqkv, qkv, CQKV);
    }

    // 2) causal flash attention
    flash_h<<<512, 128, FLASH_SMEM>>>(qkv, attn);

    // 3) output projection: grid (4, 64), 128 threads
    {
        dim3 grid(DD / 128, (BB * NN) / 128);
        gemm_h<false><<<grid, 128, GEMM_SMEM>>>(attn, wouth, bout, out, DD);
    }
}